// round 8
// baseline (speedup 1.0000x reference)
#include <cuda_runtime.h>

#define NROWS 8192
#define NDIM  512
#define ND4   128      // NDIM/4
#define NTOP  100
#define NBLK  128
#define NTHR  1024

#define SMEM_X_BYTES   (64 * ND4 * 16)          // 128 KB: block's 64 rows
#define SMEM_ACC_BYTES (16 * ND4 * 16)          // 32 KB scratch
#define SMEM_TOTAL     (SMEM_X_BYTES + SMEM_ACC_BYTES)

__device__ float4 g_spart[NBLK][ND4];
__device__ float4 g_s4v[ND4];
__device__ unsigned int g_key[NROWS];
__device__ unsigned int g_sync[4];  // [0] P1 ctr, [1] s flag, [2] key ctr, [3] done ctr

__device__ __forceinline__ unsigned int vload(unsigned int* p) {
    return *(volatile unsigned int*)p;
}

__global__ void __launch_bounds__(NTHR, 1) kFused(const float4* __restrict__ x4,
                                                  float* __restrict__ out,
                                                  float4* __restrict__ out4,
                                                  int out_size) {
    extern __shared__ char smem_raw[];
    float4* xs   = (float4*)smem_raw;                       // [64][ND4]
    float4* sacc = (float4*)(smem_raw + SMEM_X_BYTES);      // [16][ND4] scratch

    __shared__ unsigned int sh_prefix;
    __shared__ int sh_needed, sh_ncand;
    __shared__ unsigned int s_old;
    __shared__ int s_row;

    const int t    = threadIdx.x;
    const int wid  = t >> 5;          // 0..31
    const int lane = t & 31;
    const int lrow0 = wid * 2;

    // ===== P1: stream 2 rows/warp to smem, per-row 1/||x||, colsum partial ===
    float rinv0, rinv1;
    {
        const float4* r0 = x4 + (size_t)(blockIdx.x * 64 + lrow0) * ND4;
        const float4* r1 = r0 + ND4;
        float4 v0[4], v1[4];
        #pragma unroll
        for (int k = 0; k < 4; ++k) v0[k] = r0[lane + 32 * k];
        #pragma unroll
        for (int k = 0; k < 4; ++k) v1[k] = r1[lane + 32 * k];
        #pragma unroll
        for (int k = 0; k < 4; ++k) xs[lrow0 * ND4 + lane + 32 * k] = v0[k];
        #pragma unroll
        for (int k = 0; k < 4; ++k) xs[(lrow0 + 1) * ND4 + lane + 32 * k] = v1[k];

        float sq0 = 0.f, sq1 = 0.f;
        #pragma unroll
        for (int k = 0; k < 4; ++k) {
            sq0 += v0[k].x*v0[k].x + v0[k].y*v0[k].y + v0[k].z*v0[k].z + v0[k].w*v0[k].w;
            sq1 += v1[k].x*v1[k].x + v1[k].y*v1[k].y + v1[k].z*v1[k].z + v1[k].w*v1[k].w;
        }
        #pragma unroll
        for (int o = 16; o; o >>= 1) {
            sq0 += __shfl_xor_sync(0xffffffffu, sq0, o);
            sq1 += __shfl_xor_sync(0xffffffffu, sq1, o);
        }
        rinv0 = rsqrtf(sq0); rinv0 = rinv0 * (1.5f - 0.5f * sq0 * rinv0 * rinv0);
        rinv1 = rsqrtf(sq1); rinv1 = rinv1 * (1.5f - 0.5f * sq1 * rinv1 * rinv1);

        float4 acc[4];
        #pragma unroll
        for (int k = 0; k < 4; ++k) {
            acc[k].x = fmaf(v0[k].x, rinv0, v1[k].x * rinv1);
            acc[k].y = fmaf(v0[k].y, rinv0, v1[k].y * rinv1);
            acc[k].z = fmaf(v0[k].z, rinv0, v1[k].z * rinv1);
            acc[k].w = fmaf(v0[k].w, rinv0, v1[k].w * rinv1);
        }
        if (wid >= 16) {
            #pragma unroll
            for (int k = 0; k < 4; ++k) sacc[(wid - 16) * ND4 + lane + 32 * k] = acc[k];
        }
        __syncthreads();
        if (wid < 16) {
            #pragma unroll
            for (int k = 0; k < 4; ++k) {
                float4 o = sacc[wid * ND4 + lane + 32 * k];
                acc[k].x += o.x; acc[k].y += o.y; acc[k].z += o.z; acc[k].w += o.w;
                sacc[wid * ND4 + lane + 32 * k] = acc[k];
            }
        }
        __syncthreads();
        if (t < ND4) {
            float4 s = sacc[t];
            #pragma unroll
            for (int w = 1; w < 16; ++w) {
                float4 u = sacc[w * ND4 + t];
                s.x += u.x; s.y += u.y; s.z += u.z; s.w += u.w;
            }
            g_spart[blockIdx.x][t] = s;
        }
    }

    // ===== SYNC 1 (leader release/acquire): last block reduces -> g_s4v ======
    __syncthreads();
    if (t == 0) { __threadfence(); s_old = atomicAdd(&g_sync[0], 1u); }
    __syncthreads();

    if (s_old == NBLK - 1) {
        // last block: acquire partials, reduce, publish s, release flag
        if (t == 0) __threadfence();
        __syncthreads();
        int d = t & (ND4 - 1);
        int q = t >> 7;                  // 0..7, 16 partials each
        float4 s = make_float4(0.f, 0.f, 0.f, 0.f);
        #pragma unroll 4
        for (int p = q * 16; p < q * 16 + 16; ++p) {
            float4 u = g_spart[p][d];
            s.x += u.x; s.y += u.y; s.z += u.z; s.w += u.w;
        }
        sacc[q * ND4 + d] = s;
        __syncthreads();
        if (t < ND4) {
            float4 a = sacc[t];
            #pragma unroll
            for (int w = 1; w < 8; ++w) {
                float4 u = sacc[w * ND4 + t];
                a.x += u.x; a.y += u.y; a.z += u.z; a.w += u.w;
            }
            g_s4v[t] = a;
        }
        __syncthreads();
        if (t == 0) { __threadfence(); atomicExch(&g_sync[1], 1u); }
    } else {
        if (t == 0) {
            while (vload(&g_sync[1]) == 0u) __nanosleep(40);
            __threadfence();   // acquire
        }
    }
    __syncthreads();

    // ===== P3: s -> regs via smem; dots from smem-resident x; keys out =======
    {
        if (t < ND4) sacc[t] = g_s4v[t];
        __syncthreads();
        float4 sv[4];
        #pragma unroll
        for (int k = 0; k < 4; ++k) sv[k] = sacc[lane + 32 * k];

        float dot0 = 0.f, dot1 = 0.f;
        #pragma unroll
        for (int k = 0; k < 4; ++k) {
            float4 a = xs[lrow0 * ND4 + lane + 32 * k];
            float4 b = xs[(lrow0 + 1) * ND4 + lane + 32 * k];
            dot0 = fmaf(a.x, sv[k].x, dot0); dot0 = fmaf(a.y, sv[k].y, dot0);
            dot0 = fmaf(a.z, sv[k].z, dot0); dot0 = fmaf(a.w, sv[k].w, dot0);
            dot1 = fmaf(b.x, sv[k].x, dot1); dot1 = fmaf(b.y, sv[k].y, dot1);
            dot1 = fmaf(b.z, sv[k].z, dot1); dot1 = fmaf(b.w, sv[k].w, dot1);
        }
        #pragma unroll
        for (int o = 16; o; o >>= 1) {
            dot0 += __shfl_down_sync(0xffffffffu, dot0, o);
            dot1 += __shfl_down_sync(0xffffffffu, dot1, o);
        }
        if (lane == 0) {
            unsigned int u0 = __float_as_uint(dot0 * rinv0);
            unsigned int u1 = __float_as_uint(dot1 * rinv1);
            u0 = (u0 & 0x80000000u) ? ~u0 : (u0 | 0x80000000u);
            u1 = (u1 & 0x80000000u) ? ~u1 : (u1 | 0x80000000u);
            int row = blockIdx.x * 64 + lrow0;
            g_key[row]     = u0;
            g_key[row + 1] = u1;
        }
    }

    // ===== SYNC 2: keys visible. Blocks >= NTOP arrive and leave. ============
    __syncthreads();
    if (t == 0) { __threadfence(); atomicAdd(&g_sync[2], 1u); }

    if (blockIdx.x < NTOP) {
        if (t == 0) {
            while (vload(&g_sync[2]) < NBLK) __nanosleep(40);
            __threadfence();   // acquire
        }
        __syncthreads();

        // ===== P4: this block radix-selects; finds row of rank == blockIdx.x =
        int*          hist = (int*)sacc;                  // 256 ints
        unsigned int* ckey = (unsigned int*)sacc + 256;
        int*          cidx = (int*)sacc + 512;

        unsigned int k[8];
        #pragma unroll
        for (int j = 0; j < 8; ++j) k[j] = g_key[t + NTHR * j];
        if (t == 0) sh_ncand = 0;

        unsigned int prefix = 0;
        int needed = NTOP;
        #pragma unroll
        for (int round = 0; round < 4; ++round) {
            const int shift = 24 - 8 * round;
            if (t < 256) hist[t] = 0;
            __syncthreads();

            #pragma unroll
            for (int j = 0; j < 8; ++j) {
                bool ok = (round == 0) ? true : ((k[j] >> (shift + 8)) == prefix);
                unsigned int active = __ballot_sync(0xffffffffu, ok);
                if (ok) {
                    int bin = (k[j] >> shift) & 0xFF;
                    unsigned int same = __match_any_sync(active, bin);
                    if (lane == __ffs(same) - 1)
                        atomicAdd(&hist[bin], __popc(same));
                }
            }
            __syncthreads();

            if (t < 32) {
                int local[8]; int lsum = 0;
                #pragma unroll
                for (int i = 0; i < 8; ++i) { local[i] = hist[t * 8 + i]; lsum += local[i]; }
                int s = lsum;
                #pragma unroll
                for (int o = 1; o < 32; o <<= 1) {
                    int u = __shfl_up_sync(0xffffffffu, s, o);
                    if (lane >= o) s += u;
                }
                int run = s - lsum;
                #pragma unroll
                for (int i = 0; i < 8; ++i) {
                    if (run < needed && needed <= run + local[i]) {
                        sh_prefix = (prefix << 8) | (unsigned int)(t * 8 + i);
                        sh_needed = needed - run;
                    }
                    run += local[i];
                }
            }
            __syncthreads();
            prefix = sh_prefix;
            needed = sh_needed;
            __syncthreads();
        }
        unsigned int kth = prefix;   // exact 100th-smallest key

        #pragma unroll
        for (int j = 0; j < 8; ++j) {
            if (k[j] <= kth) {
                int p = atomicAdd(&sh_ncand, 1);
                if (p < 256) { ckey[p] = k[j]; cidx[p] = t + NTHR * j; }
            }
        }
        __syncthreads();
        int nc = sh_ncand < 256 ? sh_ncand : 256;

        if (t < nc) {
            unsigned int mk = ckey[t];
            int mi = cidx[t];
            int rank = 0;
            for (int j = 0; j < nc; ++j)
                rank += (ckey[j] < mk || (ckey[j] == mk && cidx[j] < mi)) ? 1 : 0;
            if (rank == blockIdx.x) s_row = mi;   // this block's assigned rank
        }
        __syncthreads();

        // ===== P5: write this block's row + index ============================
        int row = s_row;
        if (t < ND4) {
            int e = blockIdx.x * ND4 + t;
            if (4 * e + 4 <= out_size)
                out4[e] = x4[(size_t)row * ND4 + t];
        }
        if (t == 0 && NTOP * NDIM + blockIdx.x < out_size)
            out[NTOP * NDIM + blockIdx.x] = (float)row;
    }

    // ===== epilogue: last finisher resets sync state for graph replay =======
    __syncthreads();
    if (t == 0) {
        __threadfence();
        if (atomicAdd(&g_sync[3], 1u) == NBLK - 1) {
            *(volatile unsigned int*)&g_sync[0] = 0;
            *(volatile unsigned int*)&g_sync[1] = 0;
            *(volatile unsigned int*)&g_sync[2] = 0;
            __threadfence();
            *(volatile unsigned int*)&g_sync[3] = 0;
        }
    }
}

extern "C" void kernel_launch(void* const* d_in, const int* in_sizes, int n_in,
                              void* d_out, int out_size) {
    const float4* x4 = (const float4*)d_in[0];
    cudaFuncSetAttribute(kFused, cudaFuncAttributeMaxDynamicSharedMemorySize,
                         SMEM_TOTAL);
    kFused<<<NBLK, NTHR, SMEM_TOTAL>>>(x4, (float*)d_out, (float4*)d_out, out_size);
}

// round 9
// speedup vs baseline: 1.1752x; 1.1752x over previous
#include <cuda_runtime.h>

#define NROWS 8192
#define NDIM  512
#define ND4   128      // NDIM/4
#define NTOP  100
#define NBLK  128
#define NTHR  1024

#define SMEM_X_BYTES   (64 * ND4 * 16)          // 128 KB: block's 64 rows
#define SMEM_ACC_BYTES (16 * ND4 * 16)          // 32 KB scratch
#define SMEM_TOTAL     (SMEM_X_BYTES + SMEM_ACC_BYTES)

__device__ float g_s[NDIM];                     // atomic-accumulated column sum
__device__ unsigned int g_key[NROWS];
__device__ unsigned int g_sync[3];  // [0] s ctr, [1] key ctr, [2] done ctr

__device__ __forceinline__ unsigned int vload(unsigned int* p) {
    return *(volatile unsigned int*)p;
}

__global__ void __launch_bounds__(NTHR, 1) kFused(const float4* __restrict__ x4,
                                                  float* __restrict__ out,
                                                  float4* __restrict__ out4,
                                                  int out_size) {
    extern __shared__ char smem_raw[];
    float4* xs    = (float4*)smem_raw;                       // [64][ND4]
    float4* sacc  = (float4*)(smem_raw + SMEM_X_BYTES);      // [16][ND4]
    float*  saccf = (float*)sacc;

    __shared__ unsigned int sh_prefix;
    __shared__ int sh_needed, sh_ncand;
    __shared__ int s_row;

    const int t    = threadIdx.x;
    const int wid  = t >> 5;          // 0..31
    const int lane = t & 31;
    const int lrow0 = wid * 2;

    // ===== P1: stream 2 rows/warp to smem, per-row 1/||x||, colsum partial ===
    float rinv0, rinv1;
    {
        const float4* r0 = x4 + (size_t)(blockIdx.x * 64 + lrow0) * ND4;
        const float4* r1 = r0 + ND4;
        float4 v0[4], v1[4];
        #pragma unroll
        for (int k = 0; k < 4; ++k) v0[k] = r0[lane + 32 * k];
        #pragma unroll
        for (int k = 0; k < 4; ++k) v1[k] = r1[lane + 32 * k];
        #pragma unroll
        for (int k = 0; k < 4; ++k) xs[lrow0 * ND4 + lane + 32 * k] = v0[k];
        #pragma unroll
        for (int k = 0; k < 4; ++k) xs[(lrow0 + 1) * ND4 + lane + 32 * k] = v1[k];

        float sq0 = 0.f, sq1 = 0.f;
        #pragma unroll
        for (int k = 0; k < 4; ++k) {
            sq0 += v0[k].x*v0[k].x + v0[k].y*v0[k].y + v0[k].z*v0[k].z + v0[k].w*v0[k].w;
            sq1 += v1[k].x*v1[k].x + v1[k].y*v1[k].y + v1[k].z*v1[k].z + v1[k].w*v1[k].w;
        }
        #pragma unroll
        for (int o = 16; o; o >>= 1) {
            sq0 += __shfl_xor_sync(0xffffffffu, sq0, o);
            sq1 += __shfl_xor_sync(0xffffffffu, sq1, o);
        }
        rinv0 = rsqrtf(sq0); rinv0 = rinv0 * (1.5f - 0.5f * sq0 * rinv0 * rinv0);
        rinv1 = rsqrtf(sq1); rinv1 = rinv1 * (1.5f - 0.5f * sq1 * rinv1 * rinv1);

        float4 acc[4];
        #pragma unroll
        for (int k = 0; k < 4; ++k) {
            acc[k].x = fmaf(v0[k].x, rinv0, v1[k].x * rinv1);
            acc[k].y = fmaf(v0[k].y, rinv0, v1[k].y * rinv1);
            acc[k].z = fmaf(v0[k].z, rinv0, v1[k].z * rinv1);
            acc[k].w = fmaf(v0[k].w, rinv0, v1[k].w * rinv1);
        }
        if (wid >= 16) {
            #pragma unroll
            for (int k = 0; k < 4; ++k) sacc[(wid - 16) * ND4 + lane + 32 * k] = acc[k];
        }
        __syncthreads();
        if (wid < 16) {
            #pragma unroll
            for (int k = 0; k < 4; ++k) {
                float4 o = sacc[wid * ND4 + lane + 32 * k];
                acc[k].x += o.x; acc[k].y += o.y; acc[k].z += o.z; acc[k].w += o.w;
                sacc[wid * ND4 + lane + 32 * k] = acc[k];
            }
        }
        __syncthreads();
        if (t < ND4) {
            float4 s = sacc[t];
            #pragma unroll
            for (int w = 1; w < 16; ++w) {
                float4 u = sacc[w * ND4 + t];
                s.x += u.x; s.y += u.y; s.z += u.z; s.w += u.w;
            }
            sacc[t] = s;   // block partial as 512 floats at saccf[0..511]
        }
        __syncthreads();
        // atomic column-sum into g_s (512 addresses, ~128 conflicts each)
        if (t < NDIM) atomicAdd(&g_s[t], saccf[t]);
    }

    // ===== SYNC 1: counter == NBLK  =>  all atomic adds to g_s complete ======
    __syncthreads();
    if (t == 0) {
        __threadfence();                               // release my REDs
        atomicAdd(&g_sync[0], 1u);
        while (vload(&g_sync[0]) < NBLK) __nanosleep(32);
        __threadfence();                               // acquire g_s
    }
    __syncthreads();

    // ===== P3: s -> smem -> regs; dots from smem-resident x; keys out ========
    {
        if (t < NDIM) saccf[t] = g_s[t];
        __syncthreads();
        float4 sv[4];
        #pragma unroll
        for (int k = 0; k < 4; ++k) sv[k] = sacc[lane + 32 * k];

        float dot0 = 0.f, dot1 = 0.f;
        #pragma unroll
        for (int k = 0; k < 4; ++k) {
            float4 a = xs[lrow0 * ND4 + lane + 32 * k];
            float4 b = xs[(lrow0 + 1) * ND4 + lane + 32 * k];
            dot0 = fmaf(a.x, sv[k].x, dot0); dot0 = fmaf(a.y, sv[k].y, dot0);
            dot0 = fmaf(a.z, sv[k].z, dot0); dot0 = fmaf(a.w, sv[k].w, dot0);
            dot1 = fmaf(b.x, sv[k].x, dot1); dot1 = fmaf(b.y, sv[k].y, dot1);
            dot1 = fmaf(b.z, sv[k].z, dot1); dot1 = fmaf(b.w, sv[k].w, dot1);
        }
        #pragma unroll
        for (int o = 16; o; o >>= 1) {
            dot0 += __shfl_down_sync(0xffffffffu, dot0, o);
            dot1 += __shfl_down_sync(0xffffffffu, dot1, o);
        }
        if (lane == 0) {
            unsigned int u0 = __float_as_uint(dot0 * rinv0);
            unsigned int u1 = __float_as_uint(dot1 * rinv1);
            u0 = (u0 & 0x80000000u) ? ~u0 : (u0 | 0x80000000u);
            u1 = (u1 & 0x80000000u) ? ~u1 : (u1 | 0x80000000u);
            int row = blockIdx.x * 64 + lrow0;
            g_key[row]     = u0;
            g_key[row + 1] = u1;
        }
    }

    // ===== SYNC 2: keys visible. Blocks >= NTOP arrive and skip select. ======
    __syncthreads();
    if (t == 0) { __threadfence(); atomicAdd(&g_sync[1], 1u); }

    if (blockIdx.x < NTOP) {
        if (t == 0) {
            while (vload(&g_sync[1]) < NBLK) __nanosleep(32);
            __threadfence();   // acquire keys
        }
        __syncthreads();

        // ===== P4: radix-select; this block extracts rank == blockIdx.x ======
        int*          hist = (int*)sacc;
        unsigned int* ckey = (unsigned int*)sacc + 256;
        int*          cidx = (int*)sacc + 512;

        unsigned int k[8];
        #pragma unroll
        for (int j = 0; j < 8; ++j) k[j] = g_key[t + NTHR * j];
        if (t == 0) sh_ncand = 0;

        unsigned int prefix = 0;
        int needed = NTOP;
        #pragma unroll
        for (int round = 0; round < 4; ++round) {
            const int shift = 24 - 8 * round;
            if (t < 256) hist[t] = 0;
            __syncthreads();

            #pragma unroll
            for (int j = 0; j < 8; ++j) {
                bool ok = (round == 0) ? true : ((k[j] >> (shift + 8)) == prefix);
                unsigned int active = __ballot_sync(0xffffffffu, ok);
                if (ok) {
                    int bin = (k[j] >> shift) & 0xFF;
                    unsigned int same = __match_any_sync(active, bin);
                    if (lane == __ffs(same) - 1)
                        atomicAdd(&hist[bin], __popc(same));
                }
            }
            __syncthreads();

            if (t < 32) {
                int local[8]; int lsum = 0;
                #pragma unroll
                for (int i = 0; i < 8; ++i) { local[i] = hist[t * 8 + i]; lsum += local[i]; }
                int s = lsum;
                #pragma unroll
                for (int o = 1; o < 32; o <<= 1) {
                    int u = __shfl_up_sync(0xffffffffu, s, o);
                    if (lane >= o) s += u;
                }
                int run = s - lsum;
                #pragma unroll
                for (int i = 0; i < 8; ++i) {
                    if (run < needed && needed <= run + local[i]) {
                        sh_prefix = (prefix << 8) | (unsigned int)(t * 8 + i);
                        sh_needed = needed - run;
                    }
                    run += local[i];
                }
            }
            __syncthreads();
            prefix = sh_prefix;
            needed = sh_needed;
            __syncthreads();
        }
        unsigned int kth = prefix;   // exact 100th-smallest key

        #pragma unroll
        for (int j = 0; j < 8; ++j) {
            if (k[j] <= kth) {
                int p = atomicAdd(&sh_ncand, 1);
                if (p < 256) { ckey[p] = k[j]; cidx[p] = t + NTHR * j; }
            }
        }
        __syncthreads();
        int nc = sh_ncand < 256 ? sh_ncand : 256;

        if (t < nc) {
            unsigned int mk = ckey[t];
            int mi = cidx[t];
            int rank = 0;
            for (int j = 0; j < nc; ++j)
                rank += (ckey[j] < mk || (ckey[j] == mk && cidx[j] < mi)) ? 1 : 0;
            if (rank == blockIdx.x) s_row = mi;
        }
        __syncthreads();

        // ===== P5: write this block's row + index =============================
        int row = s_row;
        if (t < ND4) {
            int e = blockIdx.x * ND4 + t;
            if (4 * e + 4 <= out_size)
                out4[e] = x4[(size_t)row * ND4 + t];
        }
        if (t == 0 && NTOP * NDIM + blockIdx.x < out_size)
            out[NTOP * NDIM + blockIdx.x] = (float)row;
    }

    // ===== epilogue: last finisher resets g_s + sync state for replay ========
    __shared__ int s_reset;
    if (t == 0) {
        __threadfence();
        s_reset = (atomicAdd(&g_sync[2], 1u) == NBLK - 1) ? 1 : 0;
    }
    __syncthreads();
    if (s_reset) {
        if (t < NDIM) g_s[t] = 0.f;
        __syncthreads();
        if (t == 0) {
            *(volatile unsigned int*)&g_sync[0] = 0;
            *(volatile unsigned int*)&g_sync[1] = 0;
            __threadfence();
            *(volatile unsigned int*)&g_sync[2] = 0;
        }
    }
}

extern "C" void kernel_launch(void* const* d_in, const int* in_sizes, int n_in,
                              void* d_out, int out_size) {
    const float4* x4 = (const float4*)d_in[0];
    cudaFuncSetAttribute(kFused, cudaFuncAttributeMaxDynamicSharedMemorySize,
                         SMEM_TOTAL);
    kFused<<<NBLK, NTHR, SMEM_TOTAL>>>(x4, (float*)d_out, (float4*)d_out, out_size);
}

// round 10
// speedup vs baseline: 1.2453x; 1.0596x over previous
#include <cuda_runtime.h>

#define NROWS 8192
#define NDIM  512
#define ND4   128      // NDIM/4
#define NTOP  100
#define NBLK  128
#define NTHR  1024
#define NBIN  4096     // 12-bit histogram
#define CAP   1536     // candidate capacity (expected ~165)

#define SMEM_X_BYTES   (64 * ND4 * 16)          // 128 KB: block's 64 rows
#define SMEM_ACC_BYTES (16 * ND4 * 16)          // 32 KB scratch
#define SMEM_TOTAL     (SMEM_X_BYTES + SMEM_ACC_BYTES)

__device__ float g_s[NDIM];                     // atomic-accumulated column sum
__device__ int   g_hist[NBIN];                  // atomic-accumulated key histogram
__device__ unsigned int g_key[NROWS];
__device__ unsigned int g_sync[3];  // [0] s ctr, [1] key+hist ctr, [2] done ctr

__device__ __forceinline__ unsigned int vload(unsigned int* p) {
    return *(volatile unsigned int*)p;
}

__global__ void __launch_bounds__(NTHR, 1) kFused(const float4* __restrict__ x4,
                                                  float* __restrict__ out,
                                                  float4* __restrict__ out4,
                                                  int out_size) {
    extern __shared__ char smem_raw[];
    float4* xs    = (float4*)smem_raw;                       // [64][ND4]
    float4* sacc  = (float4*)(smem_raw + SMEM_X_BYTES);      // 32 KB scratch
    float*  saccf = (float*)sacc;

    __shared__ int  swarp[32];
    __shared__ int  sh_B, sh_ncand;
    __shared__ int  s_row;

    const int t    = threadIdx.x;
    const int wid  = t >> 5;          // 0..31
    const int lane = t & 31;
    const int lrow0 = wid * 2;

    // ===== P1: stream 2 rows/warp to smem, per-row 1/||x||, colsum partial ===
    float rinv0, rinv1;
    {
        const float4* r0 = x4 + (size_t)(blockIdx.x * 64 + lrow0) * ND4;
        const float4* r1 = r0 + ND4;
        float4 v0[4], v1[4];
        #pragma unroll
        for (int k = 0; k < 4; ++k) v0[k] = r0[lane + 32 * k];
        #pragma unroll
        for (int k = 0; k < 4; ++k) v1[k] = r1[lane + 32 * k];
        #pragma unroll
        for (int k = 0; k < 4; ++k) xs[lrow0 * ND4 + lane + 32 * k] = v0[k];
        #pragma unroll
        for (int k = 0; k < 4; ++k) xs[(lrow0 + 1) * ND4 + lane + 32 * k] = v1[k];

        float sq0 = 0.f, sq1 = 0.f;
        #pragma unroll
        for (int k = 0; k < 4; ++k) {
            sq0 += v0[k].x*v0[k].x + v0[k].y*v0[k].y + v0[k].z*v0[k].z + v0[k].w*v0[k].w;
            sq1 += v1[k].x*v1[k].x + v1[k].y*v1[k].y + v1[k].z*v1[k].z + v1[k].w*v1[k].w;
        }
        #pragma unroll
        for (int o = 16; o; o >>= 1) {
            sq0 += __shfl_xor_sync(0xffffffffu, sq0, o);
            sq1 += __shfl_xor_sync(0xffffffffu, sq1, o);
        }
        rinv0 = rsqrtf(sq0); rinv0 = rinv0 * (1.5f - 0.5f * sq0 * rinv0 * rinv0);
        rinv1 = rsqrtf(sq1); rinv1 = rinv1 * (1.5f - 0.5f * sq1 * rinv1 * rinv1);

        float4 acc[4];
        #pragma unroll
        for (int k = 0; k < 4; ++k) {
            acc[k].x = fmaf(v0[k].x, rinv0, v1[k].x * rinv1);
            acc[k].y = fmaf(v0[k].y, rinv0, v1[k].y * rinv1);
            acc[k].z = fmaf(v0[k].z, rinv0, v1[k].z * rinv1);
            acc[k].w = fmaf(v0[k].w, rinv0, v1[k].w * rinv1);
        }
        if (wid >= 16) {
            #pragma unroll
            for (int k = 0; k < 4; ++k) sacc[(wid - 16) * ND4 + lane + 32 * k] = acc[k];
        }
        __syncthreads();
        if (wid < 16) {
            #pragma unroll
            for (int k = 0; k < 4; ++k) {
                float4 o = sacc[wid * ND4 + lane + 32 * k];
                acc[k].x += o.x; acc[k].y += o.y; acc[k].z += o.z; acc[k].w += o.w;
                sacc[wid * ND4 + lane + 32 * k] = acc[k];
            }
        }
        __syncthreads();
        if (t < ND4) {
            float4 s = sacc[t];
            #pragma unroll
            for (int w = 1; w < 16; ++w) {
                float4 u = sacc[w * ND4 + t];
                s.x += u.x; s.y += u.y; s.z += u.z; s.w += u.w;
            }
            sacc[t] = s;
        }
        __syncthreads();
        if (t < NDIM) atomicAdd(&g_s[t], saccf[t]);
    }

    // ===== SYNC 1: all atomic adds to g_s complete ============================
    __syncthreads();
    if (t == 0) {
        __threadfence();
        atomicAdd(&g_sync[0], 1u);
        while (vload(&g_sync[0]) < NBLK) __nanosleep(32);
        __threadfence();
    }
    __syncthreads();

    // ===== P3: dots from smem x; keys + 12-bit histogram ======================
    {
        if (t < NDIM) saccf[t] = g_s[t];
        __syncthreads();
        float4 sv[4];
        #pragma unroll
        for (int k = 0; k < 4; ++k) sv[k] = sacc[lane + 32 * k];
        __syncthreads();                         // sv read before hist reuse

        int* hist = (int*)sacc;                  // 4096 ints (16 KB)
        #pragma unroll
        for (int j = 0; j < NBIN / NTHR; ++j) hist[t + NTHR * j] = 0;

        float dot0 = 0.f, dot1 = 0.f;
        #pragma unroll
        for (int k = 0; k < 4; ++k) {
            float4 a = xs[lrow0 * ND4 + lane + 32 * k];
            float4 b = xs[(lrow0 + 1) * ND4 + lane + 32 * k];
            dot0 = fmaf(a.x, sv[k].x, dot0); dot0 = fmaf(a.y, sv[k].y, dot0);
            dot0 = fmaf(a.z, sv[k].z, dot0); dot0 = fmaf(a.w, sv[k].w, dot0);
            dot1 = fmaf(b.x, sv[k].x, dot1); dot1 = fmaf(b.y, sv[k].y, dot1);
            dot1 = fmaf(b.z, sv[k].z, dot1); dot1 = fmaf(b.w, sv[k].w, dot1);
        }
        #pragma unroll
        for (int o = 16; o; o >>= 1) {
            dot0 += __shfl_down_sync(0xffffffffu, dot0, o);
            dot1 += __shfl_down_sync(0xffffffffu, dot1, o);
        }
        __syncthreads();                         // hist cleared
        if (lane == 0) {
            unsigned int u0 = __float_as_uint(dot0 * rinv0);
            unsigned int u1 = __float_as_uint(dot1 * rinv1);
            u0 = (u0 & 0x80000000u) ? ~u0 : (u0 | 0x80000000u);
            u1 = (u1 & 0x80000000u) ? ~u1 : (u1 | 0x80000000u);
            int row = blockIdx.x * 64 + lrow0;
            *(uint2*)&g_key[row] = make_uint2(u0, u1);
            atomicAdd(&hist[u0 >> 20], 1);
            atomicAdd(&hist[u1 >> 20], 1);
        }
        __syncthreads();
        #pragma unroll
        for (int j = 0; j < NBIN / NTHR; ++j) {
            int c = hist[t + NTHR * j];
            if (c) atomicAdd(&g_hist[t + NTHR * j], c);
        }
    }

    // ===== SYNC 2: keys + hist visible. Blocks >= NTOP just arrive. ===========
    __syncthreads();
    if (t == 0) { __threadfence(); atomicAdd(&g_sync[1], 1u); }

    if (blockIdx.x < NTOP) {
        if (t == 0) {
            while (vload(&g_sync[1]) < NBLK) __nanosleep(32);
            __threadfence();
        }
        __syncthreads();

        // ===== P4: hist scan -> boundary bin B; collect; exact rank ===========
        unsigned int* ckey = (unsigned int*)sacc;          // [CAP]
        int*          cidx = (int*)sacc + CAP;             // [CAP]

        uint4 ka = ((const uint4*)g_key)[t];               // keys 4t..4t+3
        uint4 kb = ((const uint4*)g_key)[t + 1024];        // keys 4096+4t..
        uint4 hv = ((const uint4*)g_hist)[t];              // bins 4t..4t+3
        if (t == 0) sh_ncand = 0;

        int lsum = hv.x + hv.y + hv.z + hv.w;
        int v = lsum;
        #pragma unroll
        for (int o = 1; o < 32; o <<= 1) {
            int u = __shfl_up_sync(0xffffffffu, v, o);
            if (lane >= o) v += u;
        }
        if (lane == 31) swarp[wid] = v;
        __syncthreads();
        if (t < 32) {
            int w = swarp[t];
            int vv = w;
            #pragma unroll
            for (int o = 1; o < 32; o <<= 1) {
                int u = __shfl_up_sync(0xffffffffu, vv, o);
                if (lane >= o) vv += u;
            }
            swarp[t] = vv - w;                  // exclusive warp offset
        }
        __syncthreads();
        {
            int c = swarp[wid] + (v - lsum);    // exclusive prefix for bin 4t
            int hh[4] = {(int)hv.x, (int)hv.y, (int)hv.z, (int)hv.w};
            #pragma unroll
            for (int i = 0; i < 4; ++i) {
                int c2 = c + hh[i];
                if (c < NTOP && c2 >= NTOP) sh_B = 4 * t + i;
                c = c2;
            }
        }
        __syncthreads();
        unsigned int B = (unsigned int)sh_B;

        unsigned int keys[8] = {ka.x, ka.y, ka.z, ka.w, kb.x, kb.y, kb.z, kb.w};
        #pragma unroll
        for (int j = 0; j < 8; ++j) {
            if ((keys[j] >> 20) <= B) {
                int p = atomicAdd(&sh_ncand, 1);
                if (p < CAP) {
                    ckey[p] = keys[j];
                    cidx[p] = (j < 4) ? (4 * t + j) : (4096 + 4 * t + (j - 4));
                }
            }
        }
        __syncthreads();
        int nc = sh_ncand < CAP ? sh_ncand : CAP;

        if (t < nc) {
            unsigned int mk = ckey[t];
            int mi = cidx[t];
            int rank = 0;
            for (int j = 0; j < nc; ++j)
                rank += (ckey[j] < mk || (ckey[j] == mk && cidx[j] < mi)) ? 1 : 0;
            if (rank == blockIdx.x) s_row = mi;
        }
        __syncthreads();

        // ===== P5: write this block's row + index ==============================
        int row = s_row;
        if (t < ND4) {
            int e = blockIdx.x * ND4 + t;
            if (4 * e + 4 <= out_size)
                out4[e] = x4[(size_t)row * ND4 + t];
        }
        if (t == 0 && NTOP * NDIM + blockIdx.x < out_size)
            out[NTOP * NDIM + blockIdx.x] = (float)row;
    }

    // ===== epilogue: last finisher resets g_s, g_hist, sync for replay ========
    __shared__ int s_reset;
    if (t == 0) {
        __threadfence();
        s_reset = (atomicAdd(&g_sync[2], 1u) == NBLK - 1) ? 1 : 0;
    }
    __syncthreads();
    if (s_reset) {
        if (t < NDIM) g_s[t] = 0.f;
        #pragma unroll
        for (int j = 0; j < NBIN / NTHR; ++j) g_hist[t + NTHR * j] = 0;
        __syncthreads();
        if (t == 0) {
            *(volatile unsigned int*)&g_sync[0] = 0;
            *(volatile unsigned int*)&g_sync[1] = 0;
            __threadfence();
            *(volatile unsigned int*)&g_sync[2] = 0;
        }
    }
}

extern "C" void kernel_launch(void* const* d_in, const int* in_sizes, int n_in,
                              void* d_out, int out_size) {
    const float4* x4 = (const float4*)d_in[0];
    cudaFuncSetAttribute(kFused, cudaFuncAttributeMaxDynamicSharedMemorySize,
                         SMEM_TOTAL);
    kFused<<<NBLK, NTHR, SMEM_TOTAL>>>(x4, (float*)d_out, (float4*)d_out, out_size);
}